// round 1
// baseline (speedup 1.0000x reference)
#include <cuda_runtime.h>
#include <math.h>

// Problem constants (fixed by the dataset)
#define N_NODES       65536
#define N_FEAT        64
#define N_HEADS       4
#define NTYPE         4
#define BATCH_ROWS    131072
#define ENTRIES_TOTAL (BATCH_ROWS * NTYPE)   // 524288
#define DEG           8                      // each node appears exactly 8 times
#define ALPHA         0.2f

// Scratch (allocation-free rule: __device__ globals)
__device__ int g_cnt[N_NODES];
__device__ int g_entries[ENTRIES_TOTAL];

// ---------------------------------------------------------------------------
// Kernel 0: zero the per-node counters (must run every replay)
// ---------------------------------------------------------------------------
__global__ void zero_cnt_kernel() {
    int i = blockIdx.x * blockDim.x + threadIdx.x;
    if (i < N_NODES) g_cnt[i] = 0;
}

// ---------------------------------------------------------------------------
// Kernel 1: build fixed-degree-8 CSR: for each (b,i), record packed index
//           idx = b*4 + i under target node t = batch[b*4+i].
// ---------------------------------------------------------------------------
__global__ void scatter_kernel(const int* __restrict__ batch) {
    int idx = blockIdx.x * blockDim.x + threadIdx.x;
    if (idx < ENTRIES_TOTAL) {
        int t = batch[idx];
        int p = atomicAdd(&g_cnt[t], 1);
        g_entries[t * DEG + p] = idx;
    }
}

// ---------------------------------------------------------------------------
// Kernel 2: per-node reduction.
//   16 threads per node, each owns 4 features (float4).
//   message[a] = sum_j W2[i][j][a] * feat[batch[b,j]]   (W2[i][i][a] = 0)
//   acc[a]     = max over the node's 8 entries
//   out        = leakyrelu(base + acc)
// ---------------------------------------------------------------------------
__device__ __forceinline__ void fma4(float4& m, float w, const float4& F) {
    m.x = fmaf(w, F.x, m.x);
    m.y = fmaf(w, F.y, m.y);
    m.z = fmaf(w, F.z, m.z);
    m.w = fmaf(w, F.w, m.w);
}
__device__ __forceinline__ float4 max4(const float4& a, const float4& b) {
    return make_float4(fmaxf(a.x, b.x), fmaxf(a.y, b.y),
                       fmaxf(a.z, b.z), fmaxf(a.w, b.w));
}
__device__ __forceinline__ float4 lrelu4(const float4& x) {
    // x>=0 -> x ; x<0 -> 0.2x   ==  max(x, 0.2x)
    return make_float4(fmaxf(x.x, ALPHA * x.x), fmaxf(x.y, ALPHA * x.y),
                       fmaxf(x.z, ALPHA * x.z), fmaxf(x.w, ALPHA * x.w));
}

__global__ void __launch_bounds__(256, 1) gat_kernel(
    const int4*   __restrict__ batch4,   // [BATCH_ROWS] rows of 4 node ids
    const float4* __restrict__ feat4,    // [N_NODES*16]
    const float*  __restrict__ attw,     // [4 heads, 3]
    float4*       __restrict__ out4)     // [N_NODES*64]
{
    // W2[i*16 + j*4 + a] = 0 if j==i else attw[a*3 + j - (j>i)]
    __shared__ float W2[64];
    int tid = threadIdx.x;
    if (tid < 64) {
        int a = tid & 3, j = (tid >> 2) & 3, i = tid >> 4;
        W2[tid] = (j == i) ? 0.f : attw[a * 3 + j - (j > i ? 1 : 0)];
    }
    __syncthreads();

    int t  = blockIdx.x * 16 + (tid >> 4);  // node
    int fc = tid & 15;                       // float4 chunk within the 64-feat row

    const float4 base = feat4[t * 16 + fc];

    // 8 entries for this node (two int4 broadcast loads)
    const int4* ep = reinterpret_cast<const int4*>(g_entries + t * DEG);
    int4 e0 = ep[0], e1 = ep[1];
    int ent[8] = { e0.x, e0.y, e0.z, e0.w, e1.x, e1.y, e1.z, e1.w };

    const float4 NEG = make_float4(-INFINITY, -INFINITY, -INFINITY, -INFINITY);
    float4 acc0 = NEG, acc1 = NEG, acc2 = NEG, acc3 = NEG;

#pragma unroll
    for (int e = 0; e < 8; e++) {
        int ix = ent[e];
        int b  = ix >> 2;
        int i  = ix & 3;
        int4 br = batch4[b];                 // the 4 node ids of this batch row
        const float* wp = W2 + i * 16;

        float4 m0 = make_float4(0.f, 0.f, 0.f, 0.f);
        float4 m1 = m0, m2 = m0, m3 = m0;

        // j = 0..3; when j==i the weight is 0 and the address equals `base`'s
        // line (batch[b][i] == t), so the load is an L1 hit.
        {
            float4 F  = feat4[br.x * 16 + fc];
            float4 wq = *reinterpret_cast<const float4*>(wp + 0);
            fma4(m0, wq.x, F); fma4(m1, wq.y, F); fma4(m2, wq.z, F); fma4(m3, wq.w, F);
        }
        {
            float4 F  = feat4[br.y * 16 + fc];
            float4 wq = *reinterpret_cast<const float4*>(wp + 4);
            fma4(m0, wq.x, F); fma4(m1, wq.y, F); fma4(m2, wq.z, F); fma4(m3, wq.w, F);
        }
        {
            float4 F  = feat4[br.z * 16 + fc];
            float4 wq = *reinterpret_cast<const float4*>(wp + 8);
            fma4(m0, wq.x, F); fma4(m1, wq.y, F); fma4(m2, wq.z, F); fma4(m3, wq.w, F);
        }
        {
            float4 F  = feat4[br.w * 16 + fc];
            float4 wq = *reinterpret_cast<const float4*>(wp + 12);
            fma4(m0, wq.x, F); fma4(m1, wq.y, F); fma4(m2, wq.z, F); fma4(m3, wq.w, F);
        }

        acc0 = max4(acc0, m0);
        acc1 = max4(acc1, m1);
        acc2 = max4(acc2, m2);
        acc3 = max4(acc3, m3);
    }

    // out[t, a*64 + f] -> float4 index t*64 + a*16 + fc
    int ob = t * 64 + fc;
    float4 x0 = make_float4(base.x + acc0.x, base.y + acc0.y, base.z + acc0.z, base.w + acc0.w);
    float4 x1 = make_float4(base.x + acc1.x, base.y + acc1.y, base.z + acc1.z, base.w + acc1.w);
    float4 x2 = make_float4(base.x + acc2.x, base.y + acc2.y, base.z + acc2.z, base.w + acc2.w);
    float4 x3 = make_float4(base.x + acc3.x, base.y + acc3.y, base.z + acc3.z, base.w + acc3.w);
    out4[ob + 0 * 16] = lrelu4(x0);
    out4[ob + 1 * 16] = lrelu4(x1);
    out4[ob + 2 * 16] = lrelu4(x2);
    out4[ob + 3 * 16] = lrelu4(x3);
}

// ---------------------------------------------------------------------------
// Launcher
// ---------------------------------------------------------------------------
extern "C" void kernel_launch(void* const* d_in, const int* in_sizes, int n_in,
                              void* d_out, int out_size) {
    // Identify inputs by unique element counts (robust to metadata order).
    const int*   batch = nullptr;
    const float* feat  = nullptr;
    const float* attw  = nullptr;
    for (int i = 0; i < n_in; i++) {
        if (in_sizes[i] == ENTRIES_TOTAL)        batch = (const int*)d_in[i];
        else if (in_sizes[i] == N_NODES * N_FEAT) feat  = (const float*)d_in[i];
        else if (in_sizes[i] == N_HEADS * (NTYPE - 1)) attw = (const float*)d_in[i];
    }

    zero_cnt_kernel<<<(N_NODES + 255) / 256, 256>>>();
    scatter_kernel<<<(ENTRIES_TOTAL + 255) / 256, 256>>>(batch);
    gat_kernel<<<N_NODES / 16, 256>>>(
        reinterpret_cast<const int4*>(batch),
        reinterpret_cast<const float4*>(feat),
        attw,
        reinterpret_cast<float4*>(d_out));
}

// round 2
// speedup vs baseline: 1.0073x; 1.0073x over previous
#include <cuda_runtime.h>
#include <math.h>

// Problem constants (fixed by the dataset)
#define N_NODES       65536
#define N_FEAT        64
#define N_HEADS       4
#define NTYPE         4
#define BATCH_ROWS    131072
#define ENTRIES_TOTAL (BATCH_ROWS * NTYPE)   // 524288
#define DEG           8                      // each node appears exactly 8 times
#define ALPHA         0.2f

// Scratch (allocation-free rule: __device__ globals; zero-init at module load)
__device__ int g_cnt[N_NODES];
__device__ int g_entries[ENTRIES_TOTAL];

// ---------------------------------------------------------------------------
// Kernel 1: build fixed-degree-8 CSR. g_cnt must be all-zero on entry:
//   - first execution: guaranteed by static zero-init
//   - every later execution: gat_kernel resets g_cnt[t]=0 for every node
// ---------------------------------------------------------------------------
__global__ void scatter_kernel(const int4* __restrict__ batch4) {
    int r = blockIdx.x * blockDim.x + threadIdx.x;   // batch row
    if (r < BATCH_ROWS) {
        int4 b = batch4[r];
        int base = r << 2;
        int p;
        p = atomicAdd(&g_cnt[b.x], 1); g_entries[b.x * DEG + p] = base + 0;
        p = atomicAdd(&g_cnt[b.y], 1); g_entries[b.y * DEG + p] = base + 1;
        p = atomicAdd(&g_cnt[b.z], 1); g_entries[b.z * DEG + p] = base + 2;
        p = atomicAdd(&g_cnt[b.w], 1); g_entries[b.w * DEG + p] = base + 3;
    }
}

// ---------------------------------------------------------------------------
// Kernel 2: per-node reduction (atomic-free).
//   16 threads/node, each owns a float4 chunk of the 64-feature row.
//   For each of the node's 8 (batch-row, filter-i) entries:
//     - select the 3 neighbor ids (skip j==i: weight is 0 there)
//     - message[a] = sum_k attw[a][k] * feat[neigh_k]
//     - acc[a] = max(acc[a], message[a])
//   out = leakyrelu(base + acc)
// ---------------------------------------------------------------------------
__device__ __forceinline__ void fma4(float4& m, float w, const float4& F) {
    m.x = fmaf(w, F.x, m.x);
    m.y = fmaf(w, F.y, m.y);
    m.z = fmaf(w, F.z, m.z);
    m.w = fmaf(w, F.w, m.w);
}
__device__ __forceinline__ void max4(float4& a, const float4& b) {
    a.x = fmaxf(a.x, b.x); a.y = fmaxf(a.y, b.y);
    a.z = fmaxf(a.z, b.z); a.w = fmaxf(a.w, b.w);
}
__device__ __forceinline__ float4 lrelu_add4(const float4& base, const float4& acc) {
    float4 x = make_float4(base.x + acc.x, base.y + acc.y,
                           base.z + acc.z, base.w + acc.w);
    return make_float4(fmaxf(x.x, ALPHA * x.x), fmaxf(x.y, ALPHA * x.y),
                       fmaxf(x.z, ALPHA * x.z), fmaxf(x.w, ALPHA * x.w));
}

__global__ void __launch_bounds__(256) gat_kernel(
    const int4*   __restrict__ batch4,   // [BATCH_ROWS] rows of 4 node ids
    const float4* __restrict__ feat4,    // [N_NODES*16]
    const float*  __restrict__ attw,     // [4 heads][3 neighbor positions]
    float4*       __restrict__ out4)     // [N_NODES*64]
{
    int tid = threadIdx.x;
    int t   = blockIdx.x * 16 + (tid >> 4);  // node
    int fc  = tid & 15;                      // float4 chunk within the feature row

    // 12 scalar weights, uniform across the grid
    float w[12];
#pragma unroll
    for (int k = 0; k < 12; k++) w[k] = __ldg(attw + k);

    const float4 base = feat4[t * 16 + fc];

    // this node's 8 packed entries (b*4 + i)
    const int4* ep = reinterpret_cast<const int4*>(g_entries + t * DEG);
    int4 e0 = ep[0], e1 = ep[1];
    int ent[8] = { e0.x, e0.y, e0.z, e0.w, e1.x, e1.y, e1.z, e1.w };

    // front-load all 8 batch rows to expose MLP
    int4 br[8];
#pragma unroll
    for (int e = 0; e < 8; e++) br[e] = batch4[ent[e] >> 2];

    // reset counter for next replay (entries already consumed above)
    if (fc == 0) g_cnt[t] = 0;

    const float4 NEG = make_float4(-INFINITY, -INFINITY, -INFINITY, -INFINITY);
    float4 acc0 = NEG, acc1 = NEG, acc2 = NEG, acc3 = NEG;

#pragma unroll
    for (int e = 0; e < 8; e++) {
        int  i = ent[e] & 3;
        int4 r = br[e];
        // cols[i] = all j != i, in order  -> branchless selects
        int n0 = (i == 0) ? r.y : r.x;
        int n1 = (i <= 1) ? r.z : r.y;
        int n2 = (i == 3) ? r.z : r.w;

        float4 F0 = feat4[n0 * 16 + fc];
        float4 F1 = feat4[n1 * 16 + fc];
        float4 F2 = feat4[n2 * 16 + fc];

        float4 m0 = make_float4(0.f, 0.f, 0.f, 0.f);
        float4 m1 = m0, m2 = m0, m3 = m0;
        fma4(m0, w[0],  F0); fma4(m0, w[1],  F1); fma4(m0, w[2],  F2);
        fma4(m1, w[3],  F0); fma4(m1, w[4],  F1); fma4(m1, w[5],  F2);
        fma4(m2, w[6],  F0); fma4(m2, w[7],  F1); fma4(m2, w[8],  F2);
        fma4(m3, w[9],  F0); fma4(m3, w[10], F1); fma4(m3, w[11], F2);

        max4(acc0, m0); max4(acc1, m1); max4(acc2, m2); max4(acc3, m3);
    }

    // out[t, a*64 + f] -> float4 index t*64 + a*16 + fc
    int ob = t * 64 + fc;
    out4[ob + 0 * 16] = lrelu_add4(base, acc0);
    out4[ob + 1 * 16] = lrelu_add4(base, acc1);
    out4[ob + 2 * 16] = lrelu_add4(base, acc2);
    out4[ob + 3 * 16] = lrelu_add4(base, acc3);
}

// ---------------------------------------------------------------------------
// Launcher
// ---------------------------------------------------------------------------
extern "C" void kernel_launch(void* const* d_in, const int* in_sizes, int n_in,
                              void* d_out, int out_size) {
    // Identify inputs by unique element counts (robust to metadata order).
    const int*   batch = nullptr;
    const float* feat  = nullptr;
    const float* attw  = nullptr;
    for (int i = 0; i < n_in; i++) {
        if (in_sizes[i] == ENTRIES_TOTAL)              batch = (const int*)d_in[i];
        else if (in_sizes[i] == N_NODES * N_FEAT)      feat  = (const float*)d_in[i];
        else if (in_sizes[i] == N_HEADS * (NTYPE - 1)) attw  = (const float*)d_in[i];
    }

    scatter_kernel<<<(BATCH_ROWS + 255) / 256, 256>>>(
        reinterpret_cast<const int4*>(batch));
    gat_kernel<<<N_NODES / 16, 256>>>(
        reinterpret_cast<const int4*>(batch),
        reinterpret_cast<const float4*>(feat),
        attw,
        reinterpret_cast<float4*>(d_out));
}

// round 3
// speedup vs baseline: 1.3013x; 1.2919x over previous
#include <cuda_runtime.h>
#include <math.h>

// Problem constants (fixed by the dataset)
#define N_NODES       65536
#define N_FEAT        64
#define N_HEADS       4
#define NTYPE         4
#define BATCH_ROWS    131072
#define ENTRIES_TOTAL (BATCH_ROWS * NTYPE)   // 524288
#define DEG           8                      // each node appears exactly 8 times
#define ALPHA         0.2f

typedef unsigned long long u64;

// Scratch (allocation-free rule: __device__ globals; zero-init at module load)
__device__ int  g_cnt[N_NODES];
__device__ int4 g_neigh4[N_NODES * DEG];   // per entry: (n0, n1, n2, pad)

// ---------------------------------------------------------------------------
// Kernel 1: for each batch row (x,y,z,w), emit 4 entries. Entry targeting
// node at position i carries the other 3 ids IN ORDER (== cols[i] order, so
// neighbor slot k maps directly to att weight column k).
// g_cnt must be all-zero on entry (static zero-init; gat_kernel re-zeros).
// ---------------------------------------------------------------------------
__global__ void scatter_kernel(const int4* __restrict__ batch4) {
    int r = blockIdx.x * blockDim.x + threadIdx.x;
    if (r < BATCH_ROWS) {
        int4 b = batch4[r];
        int p;
        p = atomicAdd(&g_cnt[b.x], 1); g_neigh4[b.x * DEG + p] = make_int4(b.y, b.z, b.w, 0);
        p = atomicAdd(&g_cnt[b.y], 1); g_neigh4[b.y * DEG + p] = make_int4(b.x, b.z, b.w, 0);
        p = atomicAdd(&g_cnt[b.z], 1); g_neigh4[b.z * DEG + p] = make_int4(b.x, b.y, b.w, 0);
        p = atomicAdd(&g_cnt[b.w], 1); g_neigh4[b.w * DEG + p] = make_int4(b.x, b.y, b.z, 0);
    }
}

// ---------------------------------------------------------------------------
// Packed f32x2 helpers (FFMA2 — only reachable via PTX)
// ---------------------------------------------------------------------------
__device__ __forceinline__ u64 pack2(float lo, float hi) {
    u64 r; asm("mov.b64 %0, {%1, %2};" : "=l"(r) : "f"(lo), "f"(hi)); return r;
}
__device__ __forceinline__ u64 mul2(u64 a, u64 b) {
    u64 d; asm("mul.rn.f32x2 %0, %1, %2;" : "=l"(d) : "l"(a), "l"(b)); return d;
}
__device__ __forceinline__ void fma2(u64& d, u64 a, u64 b) {
    asm("fma.rn.f32x2 %0, %1, %2, %0;" : "+l"(d) : "l"(a), "l"(b));
}
__device__ __forceinline__ void unpack2(u64 v, float& lo, float& hi) {
    asm("mov.b64 {%0, %1}, %2;" : "=f"(lo), "=f"(hi) : "l"(v));
}

// ---------------------------------------------------------------------------
// Kernel 2: per-node reduction (atomic-free).
//   16 threads/node, each owns one float4 chunk of the 64-feature row.
//   For each of the node's 8 entries: gather 3 neighbor rows, mix with the
//   4x3 attention weights (packed FFMA2), running max per head, then
//   out = leakyrelu(base + acc).
// ---------------------------------------------------------------------------
__global__ void __launch_bounds__(256, 3) gat_kernel(
    const float4* __restrict__ feat4,    // [N_NODES*16]
    const float*  __restrict__ attw,     // [4 heads][3 neighbor positions]
    float4*       __restrict__ out4)     // [N_NODES*64]
{
    int tid = threadIdx.x;
    int t   = blockIdx.x * 16 + (tid >> 4);  // node
    int fc  = tid & 15;                      // float4 chunk of the feature row

    // 12 weights, each duplicated into both halves of a packed f32x2 reg
    u64 wp[12];
#pragma unroll
    for (int k = 0; k < 12; k++) { float w = __ldg(attw + k); wp[k] = pack2(w, w); }

    const float4 base = feat4[t * 16 + fc];

    // reset counter for next replay (neigh entries of THIS replay already written)
    if (fc == 0) g_cnt[t] = 0;

    float acc[16];
#pragma unroll
    for (int k = 0; k < 16; k++) acc[k] = -INFINITY;

    const int4* np = g_neigh4 + t * DEG;

#pragma unroll
    for (int e = 0; e < 8; e++) {
        int4 ng = np[e];
        float4 F0 = feat4[ng.x * 16 + fc];
        float4 F1 = feat4[ng.y * 16 + fc];
        float4 F2 = feat4[ng.z * 16 + fc];

        u64 f0a = pack2(F0.x, F0.y), f0b = pack2(F0.z, F0.w);
        u64 f1a = pack2(F1.x, F1.y), f1b = pack2(F1.z, F1.w);
        u64 f2a = pack2(F2.x, F2.y), f2b = pack2(F2.z, F2.w);

#pragma unroll
        for (int h = 0; h < 4; h++) {
            u64 mA = mul2(wp[h * 3 + 0], f0a);
            fma2(mA, wp[h * 3 + 1], f1a);
            fma2(mA, wp[h * 3 + 2], f2a);
            u64 mB = mul2(wp[h * 3 + 0], f0b);
            fma2(mB, wp[h * 3 + 1], f1b);
            fma2(mB, wp[h * 3 + 2], f2b);

            float a0, a1, a2, a3;
            unpack2(mA, a0, a1);
            unpack2(mB, a2, a3);
            acc[h * 4 + 0] = fmaxf(acc[h * 4 + 0], a0);
            acc[h * 4 + 1] = fmaxf(acc[h * 4 + 1], a1);
            acc[h * 4 + 2] = fmaxf(acc[h * 4 + 2], a2);
            acc[h * 4 + 3] = fmaxf(acc[h * 4 + 3], a3);
        }
    }

    // out[t, h*64 + f] -> float4 index t*64 + h*16 + fc
    int ob = t * 64 + fc;
#pragma unroll
    for (int h = 0; h < 4; h++) {
        float x0 = base.x + acc[h * 4 + 0];
        float x1 = base.y + acc[h * 4 + 1];
        float x2 = base.z + acc[h * 4 + 2];
        float x3 = base.w + acc[h * 4 + 3];
        out4[ob + h * 16] = make_float4(fmaxf(x0, ALPHA * x0), fmaxf(x1, ALPHA * x1),
                                        fmaxf(x2, ALPHA * x2), fmaxf(x3, ALPHA * x3));
    }
}

// ---------------------------------------------------------------------------
// Launcher
// ---------------------------------------------------------------------------
extern "C" void kernel_launch(void* const* d_in, const int* in_sizes, int n_in,
                              void* d_out, int out_size) {
    const int*   batch = nullptr;
    const float* feat  = nullptr;
    const float* attw  = nullptr;
    for (int i = 0; i < n_in; i++) {
        if (in_sizes[i] == ENTRIES_TOTAL)              batch = (const int*)d_in[i];
        else if (in_sizes[i] == N_NODES * N_FEAT)      feat  = (const float*)d_in[i];
        else if (in_sizes[i] == N_HEADS * (NTYPE - 1)) attw  = (const float*)d_in[i];
    }

    scatter_kernel<<<(BATCH_ROWS + 255) / 256, 256>>>(
        reinterpret_cast<const int4*>(batch));
    gat_kernel<<<N_NODES / 16, 256>>>(
        reinterpret_cast<const float4*>(feat),
        attw,
        reinterpret_cast<float4*>(d_out));
}